// round 14
// baseline (speedup 1.0000x reference)
#include <cuda_runtime.h>
#include <cuda_bf16.h>

#define BQ 8
#define NQ 900
#define CC 256
#define HEADS 8
#define PP 4
#define HD 32
#define BEVH 200
#define BEVW 200
#define RADIUS 0.2f
#define MROWS 10                 // query rows per CTA; 900 = 90 * 10
#define GROUPS (NQ / MROWS)      // 90 -> grid 720 = 5x128 + 4x20 SMs, balanced
#define NRP 5                    // 5 row-pairs, no scalar remainder
#define NT 256

typedef unsigned long long ull;

__device__ __forceinline__ void fma2(ull& d, ull a, ull b) {
    asm("fma.rn.f32x2 %0, %1, %2, %0;" : "+l"(d) : "l"(a), "l"(b));
}
__device__ __forceinline__ ull pack2(float x, float y) {
    ull r; asm("mov.b64 %0, {%1, %2};" : "=l"(r) : "f"(x), "f"(y)); return r;
}
__device__ __forceinline__ float2 unpack2(ull v) {
    float2 r; asm("mov.b64 {%0, %1}, %2;" : "=f"(r.x), "=f"(r.y) : "l"(v)); return r;
}

__global__ __launch_bounds__(NT, 5)
void deform_attn_kernel(
    const float* __restrict__ query,
    const float* __restrict__ memory,
    const float* __restrict__ refp,
    const float* __restrict__ w_off,
    const float* __restrict__ b_off,
    const float* __restrict__ w_wt,
    const float* __restrict__ b_wt,
    const float* __restrict__ w_out,
    const float* __restrict__ b_out,
    float* __restrict__ out)
{
    // buf_s: all 10 rows pair-interleaved: float idx = (rp*CC + k)*2 + (r&1).
    // Holds query (phases A,B) then fused (phases D,E) — disjoint lifetimes.
    __shared__ __align__(16) float buf_s[MROWS * CC];        // 10 KB
    __shared__ __align__(16) float proj_s[MROWS][96];        // 3.75 KB
    __shared__ __align__(16) float aux[MROWS * 96];          // 3.75 KB (B partials, then sx/sy/wt)
    __shared__ __align__(8)  float ref_s[MROWS][2];
#define SXv(r, p) aux[(r) * 32 + (p)]
#define SYv(r, p) aux[320 + (r) * 32 + (p)]
#define WTv(r, p) aux[640 + (r) * 32 + (p)]

    const int bid = blockIdx.x;
    const int b = bid / GROUPS;
    const int g = bid % GROUPS;
    const int n0 = g * MROWS;
    const int t = threadIdx.x;

    // ---- Phase A: load MROWS query rows, pair-interleaved ----
    {
        const float* qbase = query + ((size_t)b * NQ + n0) * CC;
        #pragma unroll
        for (int i = 0; i < (MROWS * CC) / NT; i++) {
            const int idx = t + i * NT;
            const int r = idx >> 8;
            const int k = idx & 255;
            buf_s[((r >> 1) * CC + k) * 2 + (r & 1)] = qbase[idx];
        }
        if (t < MROWS * 2)
            ref_s[t >> 1][t & 1] = refp[((size_t)b * NQ + n0) * 2 + t];
    }
    __syncthreads();

    // ---- Phase B: projections, FFMA2 over 5 row-pairs, k-split x2.
    //      192 active threads = 96 cols x 2 k-halves. ----
    if (t < 192) {
        const int col = t % 96;
        const int kh = t / 96;
        const float* w;
        int ld;
        float bias;
        if (col < 64) { w = w_off + col; ld = 64; bias = b_off[col]; }
        else          { w = w_wt + (col - 64); ld = 32; bias = b_wt[col - 64]; }

        ull acc[NRP];
        const ull init = (kh == 0) ? pack2(bias, bias) : 0ull;
        #pragma unroll
        for (int rp = 0; rp < NRP; rp++) acc[rp] = init;

        const int k0 = kh * (CC / 2);
        for (int k = k0; k < k0 + CC / 2; k += 4) {
            const float w0 = w[(size_t)(k + 0) * ld];
            const float w1 = w[(size_t)(k + 1) * ld];
            const float w2 = w[(size_t)(k + 2) * ld];
            const float w3 = w[(size_t)(k + 3) * ld];
            const ull pw0 = pack2(w0, w0);
            const ull pw1 = pack2(w1, w1);
            const ull pw2 = pack2(w2, w2);
            const ull pw3 = pack2(w3, w3);
            #pragma unroll
            for (int rp = 0; rp < NRP; rp++) {
                const ulonglong2 fa = *reinterpret_cast<const ulonglong2*>(
                    &buf_s[(rp * CC + k) * 2]);
                const ulonglong2 fb = *reinterpret_cast<const ulonglong2*>(
                    &buf_s[(rp * CC + k + 2) * 2]);
                fma2(acc[rp], fa.x, pw0);
                fma2(acc[rp], fa.y, pw1);
                fma2(acc[rp], fb.x, pw2);
                fma2(acc[rp], fb.y, pw3);
            }
        }
        if (kh == 0) {
            #pragma unroll
            for (int rp = 0; rp < NRP; rp++) {
                const float2 v = unpack2(acc[rp]);
                proj_s[rp * 2][col] = v.x;
                proj_s[rp * 2 + 1][col] = v.y;
            }
        } else {
            #pragma unroll
            for (int rp = 0; rp < NRP; rp++) {
                const float2 v = unpack2(acc[rp]);
                aux[(rp * 2) * 96 + col] = v.x;
                aux[(rp * 2 + 1) * 96 + col] = v.y;
            }
        }
    }
    __syncthreads();
    // reduce k-halves: proj += aux (960 elements)
    {
        float* pf = &proj_s[0][0];
        #pragma unroll
        for (int i = t; i < MROWS * 96; i += NT) pf[i] += aux[i];
    }
    __syncthreads();

    // ---- Phase C: sampling coords (320 pairs) + per-head softmax (80) ----
    {
        #pragma unroll
        for (int i = 0; i < (MROWS * 32 + NT - 1) / NT; i++) {
            const int o = t + i * NT;
            if (o < MROWS * 32) {
                const int row = o / 32;
                const int pair = o % 32;
                const float rx = ref_s[row][0];
                const float ry = ref_s[row][1];
                const float ox = tanhf(proj_s[row][pair * 2 + 0]) * RADIUS;
                const float oy = tanhf(proj_s[row][pair * 2 + 1]) * RADIUS;
                SXv(row, pair) = (rx + ox) * (float)BEVW - 0.5f;
                SYv(row, pair) = (ry + oy) * (float)BEVH - 0.5f;
            }
        }
        if (t < MROWS * HEADS) {   // 80
            const int row = t >> 3;
            const int h = t & 7;
            const float l0 = proj_s[row][64 + h * 4 + 0];
            const float l1 = proj_s[row][64 + h * 4 + 1];
            const float l2 = proj_s[row][64 + h * 4 + 2];
            const float l3 = proj_s[row][64 + h * 4 + 3];
            const float m = fmaxf(fmaxf(l0, l1), fmaxf(l2, l3));
            const float e0 = __expf(l0 - m);
            const float e1 = __expf(l1 - m);
            const float e2 = __expf(l2 - m);
            const float e3 = __expf(l3 - m);
            const float inv = 1.0f / (e0 + e1 + e2 + e3);
            WTv(row, h * 4 + 0) = e0 * inv;
            WTv(row, h * 4 + 1) = e1 * inv;
            WTv(row, h * 4 + 2) = e2 * inv;
            WTv(row, h * 4 + 3) = e3 * inv;
        }
    }
    __syncthreads();

    // ---- Phase D: bilinear gather, float4, clamped unconditional loads.
    //      thread = (rowslot 4, head 8, quad 8).
    //      slot<2 handle rows {slot, slot+4, slot+8}; slot>=2 handle {slot, slot+4}. ----
    {
        const int q4 = t & 7;            // channel quad 0..7
        const int h = (t >> 3) & 7;      // head 0..7
        const int slot = t >> 6;         // 0..3
        const int nr = (slot < 2) ? 3 : 2;
        const int c = h * HD + q4 * 4;
        const float* mb = memory + (size_t)b * (BEVH * BEVW) * CC + c;
        for (int i = 0; i < nr; i++) {
            const int r = slot + i * 4;  // < MROWS by construction
            float4 acc = make_float4(0.f, 0.f, 0.f, 0.f);
            #pragma unroll
            for (int p = 0; p < PP; p++) {
                const int pair = h * PP + p;
                const float xx = SXv(r, pair);
                const float yy = SYv(r, pair);
                const float x0f = floorf(xx);
                const float y0f = floorf(yy);
                const float fx = xx - x0f;
                const float fy = yy - y0f;
                const int x0 = (int)x0f;
                const int y0 = (int)y0f;
                const int x1 = x0 + 1;
                const int y1 = y0 + 1;
                const float wx0 = (1.0f - fx) * (float)((x0 >= 0) & (x0 < BEVW));
                const float wx1 = fx * (float)((x1 >= 0) & (x1 < BEVW));
                const float wyt = (1.0f - fy) * (float)((y0 >= 0) & (y0 < BEVH));
                const float wyb = fy * (float)((y1 >= 0) & (y1 < BEVH));
                const int x0c = min(max(x0, 0), BEVW - 1);
                const int x1c = min(max(x1, 0), BEVW - 1);
                const int y0c = min(max(y0, 0), BEVH - 1);
                const int y1c = min(max(y1, 0), BEVH - 1);
                const float4 v00 = *reinterpret_cast<const float4*>(mb + (size_t)(y0c * BEVW + x0c) * CC);
                const float4 v01 = *reinterpret_cast<const float4*>(mb + (size_t)(y0c * BEVW + x1c) * CC);
                const float4 v10 = *reinterpret_cast<const float4*>(mb + (size_t)(y1c * BEVW + x0c) * CC);
                const float4 v11 = *reinterpret_cast<const float4*>(mb + (size_t)(y1c * BEVW + x1c) * CC);
                const float wt = WTv(r, pair);
                acc.x = fmaf(wt, (v00.x * wx0 + v01.x * wx1) * wyt + (v10.x * wx0 + v11.x * wx1) * wyb, acc.x);
                acc.y = fmaf(wt, (v00.y * wx0 + v01.y * wx1) * wyt + (v10.y * wx0 + v11.y * wx1) * wyb, acc.y);
                acc.z = fmaf(wt, (v00.z * wx0 + v01.z * wx1) * wyt + (v10.z * wx0 + v11.z * wx1) * wyb, acc.z);
                acc.w = fmaf(wt, (v00.w * wx0 + v01.w * wx1) * wyt + (v10.w * wx0 + v11.w * wx1) * wyb, acc.w);
            }
            const int base = ((r >> 1) * CC + c) * 2 + (r & 1);
            buf_s[base + 0] = acc.x;
            buf_s[base + 2] = acc.y;
            buf_s[base + 4] = acc.z;
            buf_s[base + 6] = acc.w;
        }
    }
    __syncthreads();

    // ---- Phase E: output projection, FFMA2 over 5 row-pairs. thread = column. ----
    {
        const int col = t;
        const float bo = b_out[col];
        ull acc[NRP];
        const ull binit = pack2(bo, bo);
        #pragma unroll
        for (int rp = 0; rp < NRP; rp++) acc[rp] = binit;

        const float* w = w_out + col;
        for (int k = 0; k < CC; k += 4) {
            const float w0 = w[(size_t)(k + 0) * CC];
            const float w1 = w[(size_t)(k + 1) * CC];
            const float w2 = w[(size_t)(k + 2) * CC];
            const float w3 = w[(size_t)(k + 3) * CC];
            const ull pw0 = pack2(w0, w0);
            const ull pw1 = pack2(w1, w1);
            const ull pw2 = pack2(w2, w2);
            const ull pw3 = pack2(w3, w3);
            #pragma unroll
            for (int rp = 0; rp < NRP; rp++) {
                const ulonglong2 fa = *reinterpret_cast<const ulonglong2*>(
                    &buf_s[(rp * CC + k) * 2]);
                const ulonglong2 fb = *reinterpret_cast<const ulonglong2*>(
                    &buf_s[(rp * CC + k + 2) * 2]);
                fma2(acc[rp], fa.x, pw0);
                fma2(acc[rp], fa.y, pw1);
                fma2(acc[rp], fb.x, pw2);
                fma2(acc[rp], fb.y, pw3);
            }
        }
        float* obase = out + ((size_t)b * NQ + n0) * CC + col;
        #pragma unroll
        for (int rp = 0; rp < NRP; rp++) {
            const float2 v = unpack2(acc[rp]);
            obase[(size_t)(rp * 2) * CC] = v.x;
            obase[(size_t)(rp * 2 + 1) * CC] = v.y;
        }
    }
#undef SXv
#undef SYv
#undef WTv
}

extern "C" void kernel_launch(void* const* d_in, const int* in_sizes, int n_in,
                              void* d_out, int out_size) {
    const float* query  = (const float*)d_in[0];
    const float* memory = (const float*)d_in[1];
    const float* refp   = (const float*)d_in[2];
    const float* w_off  = (const float*)d_in[3];
    const float* b_off  = (const float*)d_in[4];
    const float* w_wt   = (const float*)d_in[5];
    const float* b_wt   = (const float*)d_in[6];
    const float* w_out  = (const float*)d_in[7];
    const float* b_out  = (const float*)d_in[8];
    // d_in[9], d_in[10] = bev_h, bev_w (200x200, compiled in)

    float* out = (float*)d_out;
    deform_attn_kernel<<<BQ * GROUPS, NT>>>(query, memory, refp, w_off, b_off,
                                            w_wt, b_wt, w_out, b_out, out);
}